// round 5
// baseline (speedup 1.0000x reference)
#include <cuda_runtime.h>
#include <cuda_bf16.h>
#include <cstdint>

#define HH   256
#define WW   256
#define NP   (HH * WW)
#define NG   1024
#define MM   50
#define NCH  150
#define NCHF 152              // padded channels: 76 f32x2 pairs
#define TPX  16               // tile width
#define TPY  8                // tile height
#define NTX  (WW / TPX)       // 16
#define NTY  (HH / TPY)       // 32
#define NTILES (NTX * NTY)    // 512
#define HPAIR 38              // f32x2 pairs per half-thread

// Scratch (device globals; no allocation allowed)
__device__ float g_params[NG * 8];                 // cx, cy, c1, c2, c3, op
__device__ int4  g_bbox[NG];                       // conservative pixel bbox
__device__ __align__(16) float g_featT[NG * NCHF]; // [n][152] channel-major
__device__ short g_list[NTILES][NG];               // per-tile ordered gaussian lists
__device__ int   g_count[NTILES];

// ---------------------------------------------------------------------------
// Kernel 1: params+bbox (blocks 0..3) and feature transpose (blocks 4..)
// ---------------------------------------------------------------------------
__global__ void prep_all(const float* __restrict__ xyz,
                         const float* __restrict__ chol,
                         const float* __restrict__ opac,
                         const float* __restrict__ fdc,
                         const int*   __restrict__ cid_p) {
    const int tid = threadIdx.x;
    if (blockIdx.x < 4) {
        int n = blockIdx.x * 256 + tid;
        float2 xr = ((const float2*)xyz)[n];
        float x  = tanhf(xr.x);
        float y  = tanhf(xr.y);
        float l1 = chol[3 * n + 0] + 0.5f;
        float l2 = chol[3 * n + 1];
        float l3 = chol[3 * n + 2] + 0.5f;
        float a = l1 * l1;
        float b = l1 * l2;
        float c = l2 * l2 + l3 * l3;
        float det = a * c - b * b;
        float c1 = c / det;
        float c2 = -b / det;
        float c3 = a / det;
        float cx = 0.5f * ((x + 1.0f) * (float)WW - 1.0f);
        float cy = 0.5f * ((y + 1.0f) * (float)HH - 1.0f);
        float op = opac[n];
        float* p = &g_params[n * 8];
        p[0] = cx; p[1] = cy; p[2] = c1; p[3] = c2; p[4] = c3; p[5] = op;
        p[6] = 0.0f; p[7] = 0.0f;

        // alpha >= 1/255 <=> sigma <= T = ln(255*op); ellipse extents
        // hx = sqrt(2*T*Sigma_xx), hy = sqrt(2*T*Sigma_yy); +2 px margin
        int4 bb;
        float T = __logf(255.0f * op);
        if (T > 0.0f) {
            float hx = sqrtf(2.0f * T * a) + 2.0f;
            float hy = sqrtf(2.0f * T * c) + 2.0f;
            bb.x = max(0, (int)floorf(cx - hx));
            bb.y = min(WW - 1, (int)ceilf(cx + hx));
            bb.z = max(0, (int)floorf(cy - hy));
            bb.w = min(HH - 1, (int)ceilf(cy + hy));
        } else {
            bb.x = WW; bb.y = -1; bb.z = HH; bb.w = -1;
        }
        g_bbox[n] = bb;
    } else {
        int i = (blockIdx.x - 4) * 256 + tid;
        if (i < NG * NCHF) {
            int n = i / NCHF;
            int t = i - n * NCHF;
            float v = 0.0f;
            if (t < NCH) {
                int m  = t / 3;
                int cc = t - 3 * m;
                int cid = *cid_p;
                v = fdc[(((size_t)cid * MM + m) * NG + n) * 3 + cc];
            }
            g_featT[i] = v;
        }
    }
}

// ---------------------------------------------------------------------------
// Kernel 2: per-tile culled lists. One warp per tile; deterministic
// index-ordered compaction via ballot.
// ---------------------------------------------------------------------------
__global__ void build_lists() {
    const int lane = threadIdx.x & 31;
    const int tile = blockIdx.x * 8 + (threadIdx.x >> 5);
    const int tx0  = (tile & (NTX - 1)) * TPX;
    const int ty0  = (tile >> 4) * TPY;
    int off = 0;
#pragma unroll 4
    for (int j = 0; j < NG / 32; j++) {
        int g = j * 32 + lane;
        int4 bb = g_bbox[g];
        bool hit = (bb.x <= tx0 + TPX - 1) && (bb.y >= tx0) &&
                   (bb.z <= ty0 + TPY - 1) && (bb.w >= ty0);
        unsigned m = __ballot_sync(0xffffffffu, hit);
        if (hit) {
            int rank = __popc(m & ((1u << lane) - 1u));
            g_list[tile][off + rank] = (short)g;
        }
        off += __popc(m);
    }
    if (lane == 0) g_count[tile] = off;
}

// ---------------------------------------------------------------------------
// Kernel 3: barrier-free render. One CTA per 16x8 tile, 2 threads per pixel
// (half channels each), features read directly from L2-resident g_featT.
// ---------------------------------------------------------------------------
__global__ __launch_bounds__(256, 2) void render(float* __restrict__ out) {
    const int tid  = threadIdx.x;
    const int tile = blockIdx.x;
    const int tx0  = (tile & (NTX - 1)) * TPX;
    const int ty0  = (tile >> 4) * TPY;

    const int  pix  = tid >> 1;            // 0..127
    const int  half = tid & 1;             // channel half
    const float fx  = (float)(tx0 + (pix & (TPX - 1)));
    const float fy  = (float)(ty0 + (pix >> 4));

    const int count = g_count[tile];
    const short* __restrict__ list = g_list[tile];
    const float4* __restrict__ pp  = (const float4*)g_params;

    unsigned long long acc[HPAIR];
#pragma unroll
    for (int k = 0; k < HPAIR; k++) acc[k] = 0ull;

    for (int i = 0; i < count; i++) {
        int n = (int)__ldg(&list[i]);
        float4 P0 = pp[n * 2 + 0];
        float4 P1 = pp[n * 2 + 1];
        float dx = P0.x - fx;
        float dy = P0.y - fy;
        float sig = 0.5f * (P0.z * dx * dx + P1.x * dy * dy) + P0.w * dx * dy;
        float al = fminf(0.999f, P1.y * __expf(-sig));
        al = (sig >= 0.0f && al >= (1.0f / 255.0f)) ? al : 0.0f;
        if (__ballot_sync(0xffffffffu, al > 0.0f) == 0u) continue;
        unsigned long long ap;
        asm("mov.b64 %0, {%1,%1};" : "=l"(ap) : "r"(__float_as_uint(al)));
        const ulonglong2* __restrict__ fp =
            (const ulonglong2*)(g_featT + n * NCHF + half * (2 * HPAIR));
#pragma unroll
        for (int k = 0; k < HPAIR / 2; k++) {
            ulonglong2 f2 = fp[k];
            asm("fma.rn.f32x2 %0, %1, %2, %0;" : "+l"(acc[2*k])   : "l"(ap), "l"(f2.x));
            asm("fma.rn.f32x2 %0, %1, %2, %0;" : "+l"(acc[2*k+1]) : "l"(ap), "l"(f2.y));
        }
    }

    // ---- epilogue: unpack, coalesced channel-strided stores ----
    const int pofs = (ty0 + (pix >> 4)) * WW + tx0 + (pix & (TPX - 1));
#pragma unroll
    for (int k = 0; k < HPAIR; k++) {
        int kp = half * HPAIR + k;          // global pair index
        if (kp < NCH / 2) {                 // pair 75 is padding
            unsigned lo, hi;
            asm("mov.b64 {%0,%1}, %2;" : "=r"(lo), "=r"(hi) : "l"(acc[k]));
            out[(size_t)(2 * kp)     * NP + pofs] = __uint_as_float(lo);
            out[(size_t)(2 * kp + 1) * NP + pofs] = __uint_as_float(hi);
        }
    }
}

// ---------------------------------------------------------------------------
extern "C" void kernel_launch(void* const* d_in, const int* in_sizes, int n_in,
                              void* d_out, int out_size) {
    const float* xyz  = (const float*)d_in[0];  // [N,2]
    const float* chol = (const float*)d_in[1];  // [N,3]
    const float* opac = (const float*)d_in[2];  // [N,1]
    const float* fdc  = (const float*)d_in[3];  // [K,M,N,3]
    const int*   cid  = (const int*)d_in[4];    // scalar

    prep_all<<<4 + (NG * NCHF + 255) / 256, 256>>>(xyz, chol, opac, fdc, cid);
    build_lists<<<NTILES / 8, 256>>>();
    render<<<NTILES, 256>>>((float*)d_out);
}

// round 6
// speedup vs baseline: 1.0383x; 1.0383x over previous
#include <cuda_runtime.h>
#include <cuda_bf16.h>
#include <cstdint>

#define HH   256
#define WW   256
#define NP   (HH * WW)
#define NG   1024
#define MM   50
#define NCH  150
#define NCHF 152              // padded channels: 76 f32x2 pairs
#define TPX  16               // tile width
#define TPY  8                // tile height
#define NTX  (WW / TPX)       // 16
#define NTY  (HH / TPY)       // 32
#define NTILES (NTX * NTY)    // 512
#define HPAIR 38              // f32x2 pairs per half-thread
#define CHUNK 32              // gaussians staged per chunk

// Scratch (device globals; no allocation allowed)
__device__ float g_params[NG * 8];                 // cx, cy, c1, c2, c3, op
__device__ int4  g_bbox[NG];                       // conservative pixel bbox
__device__ __align__(16) float g_featT[NG * NCHF]; // [n][152] channel-major
__device__ short g_list[NTILES][NG];               // per-tile ordered lists
__device__ int   g_count[NTILES];

// ---------------------------------------------------------------------------
// Kernel 1: params+bbox (blocks 0..3); feature transpose (blocks 4..)
// Transpose is t-major / n-minor: warps read 384 contiguous bytes of fdc
// (100% sector utilization); scattered 4B writes are fire-and-forget.
// ---------------------------------------------------------------------------
__global__ void prep_all(const float* __restrict__ xyz,
                         const float* __restrict__ chol,
                         const float* __restrict__ opac,
                         const float* __restrict__ fdc,
                         const int*   __restrict__ cid_p) {
    const int tid = threadIdx.x;
    if (blockIdx.x < 4) {
        int n = blockIdx.x * 256 + tid;
        float2 xr = ((const float2*)xyz)[n];
        float x  = tanhf(xr.x);
        float y  = tanhf(xr.y);
        float l1 = chol[3 * n + 0] + 0.5f;
        float l2 = chol[3 * n + 1];
        float l3 = chol[3 * n + 2] + 0.5f;
        float a = l1 * l1;
        float b = l1 * l2;
        float c = l2 * l2 + l3 * l3;
        float det = a * c - b * b;
        float c1 = c / det;
        float c2 = -b / det;
        float c3 = a / det;
        float cx = 0.5f * ((x + 1.0f) * (float)WW - 1.0f);
        float cy = 0.5f * ((y + 1.0f) * (float)HH - 1.0f);
        float op = opac[n];
        float* p = &g_params[n * 8];
        p[0] = cx; p[1] = cy; p[2] = c1; p[3] = c2; p[4] = c3; p[5] = op;
        p[6] = 0.0f; p[7] = 0.0f;

        // zero the two padding channels of this gaussian's feature row
        g_featT[n * NCHF + NCH]     = 0.0f;
        g_featT[n * NCHF + NCH + 1] = 0.0f;

        // alpha >= 1/255 <=> sigma <= T = ln(255*op); ellipse extents
        // hx = sqrt(2*T*Sigma_xx), hy = sqrt(2*T*Sigma_yy); +2 px margin
        int4 bb;
        float T = __logf(255.0f * op);
        if (T > 0.0f) {
            float hx = sqrtf(2.0f * T * a) + 2.0f;
            float hy = sqrtf(2.0f * T * c) + 2.0f;
            bb.x = max(0, (int)floorf(cx - hx));
            bb.y = min(WW - 1, (int)ceilf(cx + hx));
            bb.z = max(0, (int)floorf(cy - hy));
            bb.w = min(HH - 1, (int)ceilf(cy + hy));
        } else {
            bb.x = WW; bb.y = -1; bb.z = HH; bb.w = -1;
        }
        g_bbox[n] = bb;
    } else {
        // i indexes (t, n) with n minor: coalesced fdc reads
        int i = (blockIdx.x - 4) * 256 + tid;
        if (i < NCH * NG) {
            int t = i >> 10;            // channel 0..149
            int n = i & (NG - 1);       // gaussian
            int m  = t / 3;
            int cc = t - 3 * m;
            int cid = *cid_p;
            float v = fdc[(((size_t)cid * MM + m) * NG + n) * 3 + cc];
            g_featT[n * NCHF + t] = v;
        }
    }
}

// ---------------------------------------------------------------------------
// Kernel 2: per-tile culled lists. One warp per tile; deterministic
// index-ordered compaction via ballot.
// ---------------------------------------------------------------------------
__global__ void build_lists() {
    const int lane = threadIdx.x & 31;
    const int tile = blockIdx.x * 8 + (threadIdx.x >> 5);
    const int tx0  = (tile & (NTX - 1)) * TPX;
    const int ty0  = (tile >> 4) * TPY;
    int off = 0;
#pragma unroll 4
    for (int j = 0; j < NG / 32; j++) {
        int g = j * 32 + lane;
        int4 bb = g_bbox[g];
        bool hit = (bb.x <= tx0 + TPX - 1) && (bb.y >= tx0) &&
                   (bb.z <= ty0 + TPY - 1) && (bb.w >= ty0);
        unsigned m = __ballot_sync(0xffffffffu, hit);
        if (hit) {
            int rank = __popc(m & ((1u << lane) - 1u));
            g_list[tile][off + rank] = (short)g;
        }
        off += __popc(m);
    }
    if (lane == 0) g_count[tile] = off;
}

// ---------------------------------------------------------------------------
// Kernel 3: render. One CTA per 16x8 tile, 2 threads per pixel (half
// channels each), SMEM-staged chunks, no in-CTA culling.
// ---------------------------------------------------------------------------
__global__ __launch_bounds__(256, 2) void render(float* __restrict__ out) {
    __shared__ __align__(16) float4 s_feat[CHUNK][NCHF / 4];  // 19 KB
    __shared__ float s_cp[CHUNK][6];

    const int tid  = threadIdx.x;
    const int tile = blockIdx.x;
    const int tx0  = (tile & (NTX - 1)) * TPX;
    const int ty0  = (tile >> 4) * TPY;

    const int  pix  = tid >> 1;            // 0..127
    const int  half = tid & 1;             // channel half
    const float fx  = (float)(tx0 + (pix & (TPX - 1)));
    const float fy  = (float)(ty0 + (pix >> 4));

    const int count = g_count[tile];
    const short* __restrict__ list = g_list[tile];

    unsigned long long acc[HPAIR];
#pragma unroll
    for (int k = 0; k < HPAIR; k++) acc[k] = 0ull;

    for (int c0 = 0; c0 < count; c0 += CHUNK) {
        int nc = min(CHUNK, count - c0);
        // stage features: nc x 38 float4
        for (int i = tid; i < nc * (NCHF / 4); i += 256) {
            int g = i / (NCHF / 4);
            int k = i - g * (NCHF / 4);
            s_feat[g][k] = ((const float4*)g_featT)[(int)list[c0 + g] * (NCHF / 4) + k];
        }
        // stage params
        if (tid < nc * 6) {
            int g = tid / 6;
            int k = tid - g * 6;
            s_cp[g][k] = g_params[(int)list[c0 + g] * 8 + k];
        }
        __syncthreads();

        for (int g = 0; g < nc; g++) {
            float cx = s_cp[g][0], cy = s_cp[g][1];
            float c1 = s_cp[g][2], c2 = s_cp[g][3], c3 = s_cp[g][4];
            float op = s_cp[g][5];
            float dx = cx - fx;
            float dy = cy - fy;
            float sig = 0.5f * (c1 * dx * dx + c3 * dy * dy) + c2 * dx * dy;
            float al = fminf(0.999f, op * __expf(-sig));
            al = (sig >= 0.0f && al >= (1.0f / 255.0f)) ? al : 0.0f;
            if (__ballot_sync(0xffffffffu, al > 0.0f) == 0u) continue;
            unsigned long long ap;
            asm("mov.b64 %0, {%1,%1};" : "=l"(ap) : "r"(__float_as_uint(al)));
            const ulonglong2* fp =
                (const ulonglong2*)((const float*)&s_feat[g][0] + half * (2 * HPAIR));
#pragma unroll
            for (int k = 0; k < HPAIR / 2; k++) {
                ulonglong2 f2 = fp[k];
                asm("fma.rn.f32x2 %0, %1, %2, %0;" : "+l"(acc[2*k])   : "l"(ap), "l"(f2.x));
                asm("fma.rn.f32x2 %0, %1, %2, %0;" : "+l"(acc[2*k+1]) : "l"(ap), "l"(f2.y));
            }
        }
        __syncthreads();
    }

    // ---- epilogue: unpack, coalesced channel-strided stores ----
    const int pofs = (ty0 + (pix >> 4)) * WW + tx0 + (pix & (TPX - 1));
#pragma unroll
    for (int k = 0; k < HPAIR; k++) {
        int kp = half * HPAIR + k;          // global pair index
        if (kp < NCH / 2) {                 // pair 75 is padding
            unsigned lo, hi;
            asm("mov.b64 {%0,%1}, %2;" : "=r"(lo), "=r"(hi) : "l"(acc[k]));
            out[(size_t)(2 * kp)     * NP + pofs] = __uint_as_float(lo);
            out[(size_t)(2 * kp + 1) * NP + pofs] = __uint_as_float(hi);
        }
    }
}

// ---------------------------------------------------------------------------
extern "C" void kernel_launch(void* const* d_in, const int* in_sizes, int n_in,
                              void* d_out, int out_size) {
    const float* xyz  = (const float*)d_in[0];  // [N,2]
    const float* chol = (const float*)d_in[1];  // [N,3]
    const float* opac = (const float*)d_in[2];  // [N,1]
    const float* fdc  = (const float*)d_in[3];  // [K,M,N,3]
    const int*   cid  = (const int*)d_in[4];    // scalar

    prep_all<<<4 + (NCH * NG + 255) / 256, 256>>>(xyz, chol, opac, fdc, cid);
    build_lists<<<NTILES / 8, 256>>>();
    render<<<NTILES, 256>>>((float*)d_out);
}

// round 7
// speedup vs baseline: 1.4885x; 1.4336x over previous
#include <cuda_runtime.h>
#include <cuda_bf16.h>
#include <cstdint>

#define HH   256
#define WW   256
#define NP   (HH * WW)
#define NG   1024
#define MM   50
#define NCH  150
#define NCHF 152                // padded channels: 76 f32x2 pairs
#define TPX  16                 // tile width
#define TPY  4                  // tile height
#define NTX  (WW / TPX)         // 16
#define NTY  (HH / TPY)         // 64
#define NTILES (NTX * NTY)      // 1024
#define QPAIR 19                // f32x2 pairs per quarter-thread
#define CHUNK 16                // gaussians staged per chunk
#define TRB  600                // transpose blocks (150*1024/256)
#define CULLB (NTILES / 8)      // 128 cull blocks (8 tiles each)

// Scratch (device globals; no allocation allowed)
__device__ float g_params[NG * 8];                 // cx, cy, c1, c2, c3, op
__device__ __align__(16) float g_featT[NG * NCHF]; // [n][152] channel-major
__device__ short g_list[NTILES][NG];               // per-tile ordered lists
__device__ int   g_count[NTILES];

// ---------------------------------------------------------------------------
// Helper: project one gaussian -> params + float bbox
// ---------------------------------------------------------------------------
__device__ __forceinline__ void project(int n,
        const float* __restrict__ xyz, const float* __restrict__ chol,
        const float* __restrict__ opac,
        float& cx, float& cy, float& c1, float& c2, float& c3, float& op,
        float4& bb) {
    float2 xr = ((const float2*)xyz)[n];
    float x  = tanhf(xr.x);
    float y  = tanhf(xr.y);
    float l1 = chol[3 * n + 0] + 0.5f;
    float l2 = chol[3 * n + 1];
    float l3 = chol[3 * n + 2] + 0.5f;
    float a = l1 * l1;
    float b = l1 * l2;
    float c = l2 * l2 + l3 * l3;
    float det = a * c - b * b;
    c1 = c / det;
    c2 = -b / det;
    c3 = a / det;
    cx = 0.5f * ((x + 1.0f) * (float)WW - 1.0f);
    cy = 0.5f * ((y + 1.0f) * (float)HH - 1.0f);
    op = opac[n];
    // alpha >= 1/255 <=> sigma <= T = ln(255*op); ellipse extents
    // hx = sqrt(2*T*Sigma_xx), hy = sqrt(2*T*Sigma_yy); +2 px margin
    float T = __logf(255.0f * op);
    if (T > 0.0f) {
        float hx = sqrtf(2.0f * T * a) + 2.0f;
        float hy = sqrtf(2.0f * T * c) + 2.0f;
        bb = make_float4(cx - hx, cx + hx, cy - hy, cy + hy);
    } else {
        bb = make_float4(1e9f, -1e9f, 1e9f, -1e9f);   // empty
    }
}

// ---------------------------------------------------------------------------
// Kernel A: blocks [0,600) feature transpose (coalesced reads);
//           blocks [600,728) bbox-in-SMEM + per-warp tile culling.
//           Block 600 also writes g_params.
// ---------------------------------------------------------------------------
__global__ void prep_and_cull(const float* __restrict__ xyz,
                              const float* __restrict__ chol,
                              const float* __restrict__ opac,
                              const float* __restrict__ fdc,
                              const int*   __restrict__ cid_p) {
    const int tid = threadIdx.x;
    if (blockIdx.x < TRB) {
        // ---- feature transpose: i = (t, n), n minor -> coalesced fdc reads ----
        int i = blockIdx.x * 256 + tid;            // < 153600 exactly
        int t = i >> 10;                           // channel 0..149
        int n = i & (NG - 1);
        int m  = t / 3;
        int cc = t - 3 * m;
        int cid = *cid_p;
        g_featT[n * NCHF + t] = fdc[(((size_t)cid * MM + m) * NG + n) * 3 + cc];
        if (t < 2)                                  // zero 2 padding channels
            g_featT[n * NCHF + NCH + t] = 0.0f;
        return;
    }

    // ---- cull blocks ----
    __shared__ __align__(16) float4 s_bb[NG];      // 16 KB float bboxes
    const int cb = blockIdx.x - TRB;               // 0..127

#pragma unroll
    for (int j = 0; j < 4; j++) {
        int n = tid + j * 256;
        float cx, cy, c1, c2, c3, op;
        float4 bb;
        project(n, xyz, chol, opac, cx, cy, c1, c2, c3, op, bb);
        s_bb[n] = bb;
        if (cb == 0) {                             // one block persists params
            float* p = &g_params[n * 8];
            p[0] = cx; p[1] = cy; p[2] = c1; p[3] = c2; p[4] = c3; p[5] = op;
            p[6] = 0.0f; p[7] = 0.0f;
        }
    }
    __syncthreads();

    const int lane = tid & 31;
    const int tile = cb * 8 + (tid >> 5);          // one warp per tile
    const float fxl = (float)((tile & (NTX - 1)) * TPX);
    const float fxh = fxl + (float)(TPX - 1);
    const float fyl = (float)((tile >> 4) * TPY);
    const float fyh = fyl + (float)(TPY - 1);
    int off = 0;
#pragma unroll 8
    for (int j = 0; j < NG / 32; j++) {
        int g = j * 32 + lane;
        float4 bb = s_bb[g];
        bool hit = (bb.x <= fxh) && (bb.y >= fxl) && (bb.z <= fyh) && (bb.w >= fyl);
        unsigned m = __ballot_sync(0xffffffffu, hit);
        if (hit) {
            int rank = __popc(m & ((1u << lane) - 1u));
            g_list[tile][off + rank] = (short)g;
        }
        off += __popc(m);
    }
    if (lane == 0) g_count[tile] = off;
}

// ---------------------------------------------------------------------------
// Kernel B: render. One CTA per 16x4 tile, 4 threads per pixel (quarter
// channels each, warp-uniform quarter), SMEM-staged chunks.
// ---------------------------------------------------------------------------
__global__ __launch_bounds__(256, 3) void render(float* __restrict__ out) {
    __shared__ __align__(16) float4 s_feat[CHUNK][NCHF / 4];  // 9.5 KB
    __shared__ float s_cp[CHUNK][6];

    const int tid  = threadIdx.x;
    const int tile = blockIdx.x;
    const int tx0  = (tile & (NTX - 1)) * TPX;
    const int ty0  = (tile >> 4) * TPY;

    const int  pix = tid & 63;             // 0..63
    const int  q   = tid >> 6;             // channel quarter, warp-uniform
    const float fx = (float)(tx0 + (pix & (TPX - 1)));
    const float fy = (float)(ty0 + (pix >> 4));

    const int count = g_count[tile];
    const short* __restrict__ list = g_list[tile];

    unsigned long long acc[QPAIR];
#pragma unroll
    for (int k = 0; k < QPAIR; k++) acc[k] = 0ull;

    for (int c0 = 0; c0 < count; c0 += CHUNK) {
        int nc = min(CHUNK, count - c0);
        for (int i = tid; i < nc * (NCHF / 4); i += 256) {
            int g = i / (NCHF / 4);
            int k = i - g * (NCHF / 4);
            s_feat[g][k] = ((const float4*)g_featT)[(int)list[c0 + g] * (NCHF / 4) + k];
        }
        if (tid < nc * 6) {
            int g = tid / 6;
            int k = tid - g * 6;
            s_cp[g][k] = g_params[(int)list[c0 + g] * 8 + k];
        }
        __syncthreads();

        for (int g = 0; g < nc; g++) {
            float cx = s_cp[g][0], cy = s_cp[g][1];
            float c1 = s_cp[g][2], c2 = s_cp[g][3], c3 = s_cp[g][4];
            float op = s_cp[g][5];
            float dx = cx - fx;
            float dy = cy - fy;
            float sig = 0.5f * (c1 * dx * dx + c3 * dy * dy) + c2 * dx * dy;
            float al = fminf(0.999f, op * __expf(-sig));
            al = (sig >= 0.0f && al >= (1.0f / 255.0f)) ? al : 0.0f;
            if (__ballot_sync(0xffffffffu, al > 0.0f) == 0u) continue;
            unsigned long long ap;
            asm("mov.b64 %0, {%1,%1};" : "=l"(ap) : "r"(__float_as_uint(al)));
            // this quarter's 19 pairs (38 floats), broadcast LDS
            const unsigned long long* fp =
                (const unsigned long long*)((const float*)&s_feat[g][0] + q * (2 * QPAIR));
#pragma unroll
            for (int k = 0; k < QPAIR; k++) {
                unsigned long long f2 = fp[k];
                asm("fma.rn.f32x2 %0, %1, %2, %0;" : "+l"(acc[k]) : "l"(ap), "l"(f2));
            }
        }
        __syncthreads();
    }

    // ---- epilogue: full-warp single-channel 128B stores ----
    const int pofs = (ty0 + (pix >> 4)) * WW + tx0 + (pix & (TPX - 1));
#pragma unroll
    for (int k = 0; k < QPAIR; k++) {
        int kp = q * QPAIR + k;             // global pair index
        if (kp < NCH / 2) {                 // pair 75 is padding
            unsigned lo, hi;
            asm("mov.b64 {%0,%1}, %2;" : "=r"(lo), "=r"(hi) : "l"(acc[k]));
            out[(size_t)(2 * kp)     * NP + pofs] = __uint_as_float(lo);
            out[(size_t)(2 * kp + 1) * NP + pofs] = __uint_as_float(hi);
        }
    }
}

// ---------------------------------------------------------------------------
extern "C" void kernel_launch(void* const* d_in, const int* in_sizes, int n_in,
                              void* d_out, int out_size) {
    const float* xyz  = (const float*)d_in[0];  // [N,2]
    const float* chol = (const float*)d_in[1];  // [N,3]
    const float* opac = (const float*)d_in[2];  // [N,1]
    const float* fdc  = (const float*)d_in[3];  // [K,M,N,3]
    const int*   cid  = (const int*)d_in[4];    // scalar

    prep_and_cull<<<TRB + CULLB, 256>>>(xyz, chol, opac, fdc, cid);
    render<<<NTILES, 256>>>((float*)d_out);
}